// round 14
// baseline (speedup 1.0000x reference)
#include <cuda_runtime.h>
#include <math.h>

// Problem constants
#define Bn   64
#define Sn   256
#define Dn   300
#define NWn  8192
#define CLn  16
#define CDn  30
#define CHn  30
#define Hn   128
#define Tn   17
#define INW0 330   // D + CH
#define G3   384   // 3*H
#define G6   768   // 2 dirs * 3H
#define XPW  1024  // packed xg width: 2 dirs * 128 units * 4 (r,z,n,pad)

typedef unsigned long long ull;

// ---------------- f32x2 / fast-math helpers ----------------
__device__ __forceinline__ ull pk2(float lo, float hi) {
    ull r; asm("mov.b64 %0,{%1,%2};" : "=l"(r) : "f"(lo), "f"(hi)); return r;
}
__device__ __forceinline__ void ffma2(ull& acc, ull a, ull b) {
    asm("fma.rn.f32x2 %0,%1,%2,%0;" : "+l"(acc) : "l"(a), "l"(b));
}
__device__ __forceinline__ void upk2(ull v, float& lo, float& hi) {
    asm("mov.b64 {%0,%1},%2;" : "=f"(lo), "=f"(hi) : "l"(v));
}
__device__ __forceinline__ float tanh_fast(float v) {
    float r; asm("tanh.approx.f32 %0,%1;" : "=f"(r) : "f"(v)); return r;
}
__device__ __forceinline__ float sigmoid_fast(float v) {
    return fmaf(tanh_fast(0.5f * v), 0.5f, 0.5f);
}
__device__ __forceinline__ unsigned f2tf32(float f) {
    unsigned u; asm("cvt.rna.tf32.f32 %0,%1;" : "=r"(u) : "f"(f)); return u;
}

// ---------------- device scratch (static, no allocation) ----------------
__device__ float g_tokenc[(NWn + 1) * CHn];
__device__ float g_texts[(size_t)Bn * Sn * INW0];
__device__ float g_xg[(size_t)Bn * Sn * XPW];      // packed: [m][dir*512 + u*4 + gate]
__device__ float g_h0[(size_t)Bn * Sn * 256];
__device__ float g_h1[(size_t)Bn * Sn * 256];
__device__ float g_mlp[(size_t)Bn * Sn * Hn];
__device__ float g_emis[(size_t)Bn * Sn * Tn + 64];
__device__ float g_llh[Bn];
__device__ float g_w1t[Hn * 256];   // transposed mlp_w1: [128][256]

// ---------------- char CNN (256 threads, better occupancy) ----------------
__global__ void char_cnn_kernel(const float* __restrict__ char_emb,
                                const float* __restrict__ conv_w,
                                const float* __restrict__ conv_b,
                                const int* __restrict__ words) {
    __shared__ float s_emb[CLn + 2][CDn];
    __shared__ float s_w[CHn * CDn * 3];
    __shared__ float s_out[CHn * CLn];
    __shared__ int   s_idx[CLn];
    int tid = threadIdx.x;
    int blk = blockIdx.x;
    if (blk == 0) {
        if (tid < CHn) g_tokenc[tid] = 0.f;
        return;
    }
    int w = blk - 1;
    if (tid < CLn) s_idx[tid] = words[w * CLn + tid];
    for (int i = tid; i < CHn * CDn * 3; i += 256) s_w[i] = conv_w[i];
    if (tid < CDn) { s_emb[0][tid] = 0.f; s_emb[CLn + 1][tid] = 0.f; }
    __syncthreads();
    for (int i = tid; i < CLn * CDn; i += 256) {
        int t = i / CDn, d = i % CDn;
        s_emb[t + 1][d] = char_emb[s_idx[t] * CDn + d];
    }
    __syncthreads();
    for (int i = tid; i < CHn * CLn; i += 256) {
        int ch = i / CLn, t = i % CLn;
        float acc = conv_b[ch];
        const float* wr = &s_w[ch * CDn * 3];
#pragma unroll
        for (int d = 0; d < CDn; ++d) {
            acc += s_emb[t][d]     * wr[d * 3 + 0];
            acc += s_emb[t + 1][d] * wr[d * 3 + 1];
            acc += s_emb[t + 2][d] * wr[d * 3 + 2];
        }
        s_out[ch * CLn + t] = fmaxf(acc, 0.f);
    }
    __syncthreads();
    if (tid < CHn) {
        float m = s_out[tid * CLn];
#pragma unroll
        for (int t = 1; t < CLn; ++t) m = fmaxf(m, s_out[tid * CLn + t]);
        g_tokenc[(w + 1) * CHn + tid] = m;
    }
}

// ---------------- build texts ----------------
__global__ void build_texts_kernel(const float* __restrict__ word_emb,
                                   const int* __restrict__ tokens,
                                   const int* __restrict__ cwi) {
    int m = blockIdx.x;
    int tid = threadIdx.x;
    int tok = tokens[m];
    int ci = cwi[m];
    if (tid < Dn)
        g_texts[(size_t)m * INW0 + tid] = word_emb[(size_t)tok * Dn + tid];
    else if (tid < INW0)
        g_texts[(size_t)m * INW0 + tid] = g_tokenc[ci * CHn + (tid - Dn)];
}

// ---------------- transpose mlp_w1 [256][128] -> [128][256] ----------------
__global__ void transpose_w1_kernel(const float* __restrict__ w1) {
    __shared__ float tile[32][33];
    int bx = blockIdx.x % 4, by = blockIdx.x / 4;
    int tx = threadIdx.x % 32, ty = threadIdx.x / 32;
#pragma unroll
    for (int r = 0; r < 4; ++r) {
        int row = ty + r * 8;
        tile[row][tx] = w1[(size_t)(by * 32 + row) * Hn + bx * 32 + tx];
    }
    __syncthreads();
#pragma unroll
    for (int r = 0; r < 4; ++r) {
        int row = ty + r * 8;
        g_w1t[(size_t)(bx * 32 + row) * 256 + by * 32 + tx] = tile[tx][row];
    }
}

// ---------------- tf32 GEMM: 128x64 tile, reg-prefetch (R11/R13 proven) ----------------
// C[M][N] = A[M][K] * W^T + bias; W is [N][K]. M%128==0, N%64==0.
// xpack=1: store into packed xg layout [row][dir*512 + u*4 + gate] (stride XPW).
#define PA 133
#define PW 69
__global__ void __launch_bounds__(256)
gemm_tf32_kernel(const float* __restrict__ A,
                 const float* __restrict__ W,
                 const float* __restrict__ bias,
                 float* __restrict__ C,
                 int M, int N, int K, int relu, int xpack) {
    __shared__ float As[16][PA];
    __shared__ float Ws[16][PW];
    int tid = threadIdx.x;
    int warp = tid >> 5, lane = tid & 31;
    int wm = warp & 3, wn = warp >> 2;
    int group = lane >> 2, tig = lane & 3;
    int m0 = blockIdx.y * 128, n0 = blockIdx.x * 64;
    float acc[2][4][4];
#pragma unroll
    for (int i = 0; i < 2; ++i)
#pragma unroll
        for (int j = 0; j < 4; ++j)
#pragma unroll
            for (int c = 0; c < 4; ++c) acc[i][j][c] = 0.f;

    int lkk = tid % 16;
    int li = tid / 16;
    int ktiles = (K + 15) / 16;
    float rA[8], rW[4];
#pragma unroll
    for (int l = 0; l < 8; ++l)
        rA[l] = (lkk < K) ? A[(size_t)(m0 + li + l * 16) * K + lkk] : 0.f;
#pragma unroll
    for (int l = 0; l < 4; ++l)
        rW[l] = (lkk < K) ? W[(size_t)(n0 + li + l * 16) * K + lkk] : 0.f;

    for (int kt = 0; kt < ktiles; ++kt) {
#pragma unroll
        for (int l = 0; l < 8; ++l)
            As[lkk][li + l * 16] = __uint_as_float(f2tf32(rA[l]));
#pragma unroll
        for (int l = 0; l < 4; ++l)
            Ws[lkk][li + l * 16] = __uint_as_float(f2tf32(rW[l]));
        __syncthreads();
        if (kt + 1 < ktiles) {
            int k = (kt + 1) * 16 + lkk;
#pragma unroll
            for (int l = 0; l < 8; ++l)
                rA[l] = (k < K) ? A[(size_t)(m0 + li + l * 16) * K + k] : 0.f;
#pragma unroll
            for (int l = 0; l < 4; ++l)
                rW[l] = (k < K) ? W[(size_t)(n0 + li + l * 16) * K + k] : 0.f;
        }
#pragma unroll
        for (int k8 = 0; k8 < 2; ++k8) {
            int kb = k8 * 8;
            unsigned a[2][4], b[4][2];
#pragma unroll
            for (int mt = 0; mt < 2; ++mt) {
                int mb = wm * 32 + mt * 16;
                a[mt][0] = __float_as_uint(As[kb + tig][mb + group]);
                a[mt][1] = __float_as_uint(As[kb + tig][mb + group + 8]);
                a[mt][2] = __float_as_uint(As[kb + tig + 4][mb + group]);
                a[mt][3] = __float_as_uint(As[kb + tig + 4][mb + group + 8]);
            }
#pragma unroll
            for (int nt = 0; nt < 4; ++nt) {
                int nb = wn * 32 + nt * 8;
                b[nt][0] = __float_as_uint(Ws[kb + tig][nb + group]);
                b[nt][1] = __float_as_uint(Ws[kb + tig + 4][nb + group]);
            }
#pragma unroll
            for (int mt = 0; mt < 2; ++mt)
#pragma unroll
                for (int nt = 0; nt < 4; ++nt) {
                    asm volatile(
                        "mma.sync.aligned.m16n8k8.row.col.f32.tf32.tf32.f32 "
                        "{%0,%1,%2,%3},{%4,%5,%6,%7},{%8,%9},{%0,%1,%2,%3};"
                        : "+f"(acc[mt][nt][0]), "+f"(acc[mt][nt][1]),
                          "+f"(acc[mt][nt][2]), "+f"(acc[mt][nt][3])
                        : "r"(a[mt][0]), "r"(a[mt][1]), "r"(a[mt][2]), "r"(a[mt][3]),
                          "r"(b[nt][0]), "r"(b[nt][1]));
                }
        }
        __syncthreads();
    }
    // epilogue
#pragma unroll
    for (int mt = 0; mt < 2; ++mt) {
        int row = m0 + wm * 32 + mt * 16 + group;
#pragma unroll
        for (int nt = 0; nt < 4; ++nt) {
            int col = n0 + wn * 32 + nt * 8 + 2 * tig;
            float b0 = bias[col], b1 = bias[col + 1];
            float v0 = acc[mt][nt][0] + b0;
            float v1 = acc[mt][nt][1] + b1;
            float v2 = acc[mt][nt][2] + b0;
            float v3 = acc[mt][nt][3] + b1;
            if (relu) {
                v0 = fmaxf(v0, 0.f); v1 = fmaxf(v1, 0.f);
                v2 = fmaxf(v2, 0.f); v3 = fmaxf(v3, 0.f);
            }
            if (xpack) {
                // col -> dir, gate, unit; packed idx = dir*512 + u*4 + gate
                int dir = (col >= 384) ? 1 : 0;
                int rem = col - dir * 384;
                int gate = rem >> 7;
                int u = rem & 127;
                int idx0 = dir * 512 + u * 4 + gate;
                int rem1 = rem + 1;              // col+1 same dir (see analysis)
                int gate1 = rem1 >> 7;
                int u1 = rem1 & 127;
                int idx1 = dir * 512 + u1 * 4 + gate1;
                C[(size_t)row * XPW + idx0]       = v0;
                C[(size_t)row * XPW + idx1]       = v1;
                C[(size_t)(row + 8) * XPW + idx0] = v2;
                C[(size_t)(row + 8) * XPW + idx1] = v3;
            } else {
                C[(size_t)row * N + col]           = v0;
                C[(size_t)row * N + col + 1]       = v1;
                C[(size_t)(row + 8) * N + col]     = v2;
                C[(size_t)(row + 8) * N + col + 1] = v3;
            }
        }
    }
}

// ---------------- scalar SGEMM 128x64 (emissions; R8 proven) ----------------
__global__ void gemm_kernel(const float* __restrict__ A,
                            const float* __restrict__ W,
                            const float* __restrict__ bias,
                            float* __restrict__ C,
                            int M, int N, int K, int relu, int wNK) {
    __shared__ float As[16][129];
    __shared__ float Ws[16][65];
    int tid = threadIdx.x;
    int tx = tid % 16, ty = tid / 16;
    int m0 = blockIdx.y * 128, n0 = blockIdx.x * 64;
    float acc[8][4] = {};
    int ktiles = (K + 15) / 16;
    for (int kt = 0; kt < ktiles; ++kt) {
        int k0 = kt * 16;
#pragma unroll
        for (int l = 0; l < 8; ++l) {
            int e = tid + l * 256;
            int kk = e % 16, i = e / 16;
            int m = m0 + i, k = k0 + kk;
            As[kk][i] = (k < K && m < M) ? A[(size_t)m * K + k] : 0.f;
        }
#pragma unroll
        for (int l = 0; l < 4; ++l) {
            int e = tid + l * 256;
            int kk = e % 16, i = e / 16;
            int n = n0 + i, k = k0 + kk;
            float wv = 0.f;
            if (k < K && n < N)
                wv = wNK ? W[(size_t)n * K + k] : W[(size_t)k * N + n];
            Ws[kk][i] = wv;
        }
        __syncthreads();
#pragma unroll
        for (int kk = 0; kk < 16; ++kk) {
            float a[8], b[4];
#pragma unroll
            for (int i = 0; i < 8; ++i) a[i] = As[kk][ty * 8 + i];
#pragma unroll
            for (int j = 0; j < 4; ++j) b[j] = Ws[kk][tx * 4 + j];
#pragma unroll
            for (int i = 0; i < 8; ++i)
#pragma unroll
                for (int j = 0; j < 4; ++j)
                    acc[i][j] += a[i] * b[j];
        }
        __syncthreads();
    }
#pragma unroll
    for (int i = 0; i < 8; ++i) {
        int m = m0 + ty * 8 + i;
        if (m >= M) continue;
#pragma unroll
        for (int j = 0; j < 4; ++j) {
            int n = n0 + tx * 4 + j;
            if (n >= N) continue;
            float v = acc[i][j] + bias[n];
            if (relu) v = fmaxf(v, 0.f);
            C[(size_t)m * N + n] = v;
        }
    }
}

// ---------------- GRU scan: quad K-split, packed float4 x loads ----------------
#define GT2 512
__global__ void __launch_bounds__(GT2, 1)
gru_kernel(const float* __restrict__ xg,    // packed [B*S][XPW]
           const float* __restrict__ w_hh,  // [2][384][128]
           const float* __restrict__ b_hh,  // [2][384]
           const int* __restrict__ lens,
           float* __restrict__ out) {       // [B*S][256]
    __shared__ __align__(16) float sh_h[2][Hn];
    int tid = threadIdx.x;
    int u = tid >> 2;
    int q = tid & 3;
    int dir = blockIdx.x / Bn;
    int b = blockIdx.x % Bn;

    ull wr2[48];
    {
        const float* Wd = w_hh + (size_t)dir * G3 * Hn;
#pragma unroll
        for (int gg = 0; gg < 3; ++gg) {
            const float* row = Wd + (size_t)(gg * Hn + u) * Hn + 4 * q;
#pragma unroll
            for (int i = 0; i < 8; ++i) {
                ulonglong2 v = *(const ulonglong2*)(row + 16 * i);
                wr2[gg * 16 + 2 * i]     = v.x;
                wr2[gg * 16 + 2 * i + 1] = v.y;
            }
        }
    }
    float br = b_hh[dir * G3 + u];
    float bz = b_hh[dir * G3 + Hn + u];
    float bnn = b_hh[dir * G3 + 2 * Hn + u];
    int len = lens[b];
    const float* xgb = xg + (size_t)b * Sn * XPW + dir * 512 + 4 * u;
    float* outb = out + (size_t)b * Sn * 256 + dir * Hn;

    if (tid < Hn) { sh_h[0][tid] = 0.f; sh_h[1][tid] = 0.f; }

    int s0 = dir ? (Sn - 1) : 0;
    float4 xv_n = *(const float4*)(xgb + (size_t)s0 * XPW);
    __syncthreads();

    int p = 0;
    for (int t = 0; t < Sn; ++t) {
        int s = dir ? (Sn - 1 - t) : t;
        float4 xv = xv_n;
        if (t + 1 < Sn) {
            int sn = dir ? (s - 1) : (s + 1);
            xv_n = *(const float4*)(xgb + (size_t)sn * XPW);
        }
        const ulonglong2* hbp = (const ulonglong2*)(&sh_h[p][0] + 4 * q);
        ull ar = pk2(0.f, 0.f), az = ar, an = ar;
#pragma unroll
        for (int i = 0; i < 8; ++i) {
            ulonglong2 hv2 = hbp[i * 4];
            ffma2(ar, wr2[2 * i],          hv2.x);
            ffma2(az, wr2[16 + 2 * i],     hv2.x);
            ffma2(an, wr2[32 + 2 * i],     hv2.x);
            ffma2(ar, wr2[2 * i + 1],      hv2.y);
            ffma2(az, wr2[16 + 2 * i + 1], hv2.y);
            ffma2(an, wr2[32 + 2 * i + 1], hv2.y);
        }
        float lo, hi;
        upk2(ar, lo, hi); float hr = lo + hi;
        upk2(az, lo, hi); float hz = lo + hi;
        upk2(an, lo, hi); float hn = lo + hi;
        hr += __shfl_xor_sync(0xffffffffu, hr, 1);
        hz += __shfl_xor_sync(0xffffffffu, hz, 1);
        hn += __shfl_xor_sync(0xffffffffu, hn, 1);
        hr += __shfl_xor_sync(0xffffffffu, hr, 2);
        hz += __shfl_xor_sync(0xffffffffu, hz, 2);
        hn += __shfl_xor_sync(0xffffffffu, hn, 2);
        float hp = sh_h[p][u];
        float r = sigmoid_fast(xv.x + hr + br);
        float z = sigmoid_fast(xv.y + hz + bz);
        float n = tanh_fast(fmaf(r, hn + bnn, xv.z));
        float hv = (s < len) ? ((1.f - z) * n + z * hp) : hp;
        if (q == 0) sh_h[p ^ 1][u] = hv;
        if (q == 1) outb[(size_t)s * 256 + u] = hv;
        p ^= 1;
        __syncthreads();
    }
}

// ---------------- CRF (fast exp/log) ----------------
__global__ void crf_kernel(const float* __restrict__ start,
                           const float* __restrict__ end_,
                           const float* __restrict__ trans,
                           const int* __restrict__ target,
                           const int* __restrict__ lens) {
    int b = blockIdx.x, lane = threadIdx.x;
    const float* E = g_emis + (size_t)b * Sn * Tn;
    const int* tgt = target + b * Sn;
    int len = lens[b];

    float partial = 0.f;
    for (int s = 1 + lane; s < Sn; s += 32) {
        if (s < len)
            partial += trans[tgt[s - 1] * Tn + tgt[s]] + E[s * Tn + tgt[s]];
    }
#pragma unroll
    for (int o = 16; o; o >>= 1) partial += __shfl_down_sync(0xffffffffu, partial, o);

    float tc[Tn];
    float alpha = -1e30f;
    if (lane < Tn) {
        alpha = start[lane] + E[lane];
#pragma unroll
        for (int i = 0; i < Tn; ++i) tc[i] = trans[i * Tn + lane];
    } else {
#pragma unroll
        for (int i = 0; i < Tn; ++i) tc[i] = 0.f;
    }
    for (int s = 1; s < Sn; ++s) {
        float av[Tn];
        float mx = -1e30f;
#pragma unroll
        for (int i = 0; i < Tn; ++i) {
            av[i] = __shfl_sync(0xffffffffu, alpha, i) + tc[i];
            mx = fmaxf(mx, av[i]);
        }
        float sum = 0.f;
#pragma unroll
        for (int i = 0; i < Tn; ++i) sum += __expf(av[i] - mx);
        float e = (lane < Tn) ? E[s * Tn + lane] : 0.f;
        float nw = mx + __logf(sum) + e;
        if (lane < Tn && s < len) alpha = nw;
    }
    float v = (lane < Tn) ? alpha + end_[lane] : -1e30f;
    float mx = v;
#pragma unroll
    for (int o = 16; o; o >>= 1) mx = fmaxf(mx, __shfl_xor_sync(0xffffffffu, mx, o));
    float se = __expf(v - mx);
#pragma unroll
    for (int o = 16; o; o >>= 1) se += __shfl_xor_sync(0xffffffffu, se, o);
    float logz = mx + __logf(se);
    if (lane == 0) {
        float score = partial + start[tgt[0]] + E[tgt[0]] + end_[tgt[len - 1]];
        g_llh[b] = score - logz;
    }
}

__global__ void finalize_kernel(const int* __restrict__ lens, float* __restrict__ out) {
    float sl = 0.f;
    float smk = 0.f;
    for (int b = 0; b < Bn; ++b) { sl += g_llh[b]; smk += (float)lens[b]; }
    out[0] = -sl / smk;
}

// ---------------- launch ----------------
extern "C" void kernel_launch(void* const* d_in, const int* in_sizes, int n_in,
                              void* d_out, int out_size) {
    const float* char_emb  = (const float*)d_in[0];
    const float* conv_w    = (const float*)d_in[1];
    const float* conv_b    = (const float*)d_in[2];
    const float* word_emb  = (const float*)d_in[3];
    const float* w_ih_l0   = (const float*)d_in[4];
    const float* w_hh_l0   = (const float*)d_in[5];
    const float* b_ih_l0   = (const float*)d_in[6];
    const float* b_hh_l0   = (const float*)d_in[7];
    const float* w_ih_l1   = (const float*)d_in[8];
    const float* w_hh_l1   = (const float*)d_in[9];
    const float* b_ih_l1   = (const float*)d_in[10];
    const float* b_hh_l1   = (const float*)d_in[11];
    const float* mlp_w1    = (const float*)d_in[12];
    const float* mlp_b1    = (const float*)d_in[13];
    const float* mlp_w2    = (const float*)d_in[14];
    const float* mlp_b2    = (const float*)d_in[15];
    const float* crf_start = (const float*)d_in[16];
    const float* crf_end   = (const float*)d_in[17];
    const float* crf_trans = (const float*)d_in[18];
    const int* char_words  = (const int*)d_in[19];
    const int* cwi         = (const int*)d_in[21];
    const int* tokens      = (const int*)d_in[22];
    const int* tokens_len  = (const int*)d_in[23];
    const int* target      = (const int*)d_in[24];
    float* out = (float*)d_out;

    void* pv;
    cudaGetSymbolAddress(&pv, g_texts); float* p_texts = (float*)pv;
    cudaGetSymbolAddress(&pv, g_xg);    float* p_xg    = (float*)pv;
    cudaGetSymbolAddress(&pv, g_h0);    float* p_h0    = (float*)pv;
    cudaGetSymbolAddress(&pv, g_h1);    float* p_h1    = (float*)pv;
    cudaGetSymbolAddress(&pv, g_mlp);   float* p_mlp   = (float*)pv;
    cudaGetSymbolAddress(&pv, g_emis);  float* p_emis  = (float*)pv;
    cudaGetSymbolAddress(&pv, g_w1t);   float* p_w1t   = (float*)pv;

    const int M = Bn * Sn;  // 16384

    char_cnn_kernel<<<NWn + 1, 256>>>(char_emb, conv_w, conv_b, char_words);
    transpose_w1_kernel<<<32, 256>>>(mlp_w1);
    build_texts_kernel<<<M, 352>>>(word_emb, tokens, cwi);
    gemm_tf32_kernel<<<dim3(G6 / 64, M / 128), 256>>>(p_texts, w_ih_l0, b_ih_l0, p_xg,
                                                      M, G6, INW0, 0, 1);
    gru_kernel<<<2 * Bn, GT2>>>(p_xg, w_hh_l0, b_hh_l0, tokens_len, p_h0);
    gemm_tf32_kernel<<<dim3(G6 / 64, M / 128), 256>>>(p_h0, w_ih_l1, b_ih_l1, p_xg,
                                                      M, G6, 256, 0, 1);
    gru_kernel<<<2 * Bn, GT2>>>(p_xg, w_hh_l1, b_hh_l1, tokens_len, p_h1);
    gemm_tf32_kernel<<<dim3(Hn / 64, M / 128), 256>>>(p_h1, p_w1t, mlp_b1, p_mlp,
                                                      M, Hn, 256, 1, 0);
    gemm_kernel<<<dim3(1, M / 128), 256>>>(p_mlp, mlp_w2, mlp_b2, p_emis,
                                           M, Tn, Hn, 0, 0);
    crf_kernel<<<Bn, 32>>>(crf_start, crf_end, crf_trans, target, tokens_len);
    finalize_kernel<<<1, 1>>>(tokens_len, out);
}

// round 15
// speedup vs baseline: 1.2599x; 1.2599x over previous
#include <cuda_runtime.h>
#include <math.h>

// Problem constants
#define Bn   64
#define Sn   256
#define Dn   300
#define NWn  8192
#define CLn  16
#define CDn  30
#define CHn  30
#define Hn   128
#define Tn   17
#define INW0 330   // D + CH
#define G3   384   // 3*H
#define G6   768   // 2 dirs * 3H

typedef unsigned long long ull;

// ---------------- f32x2 / fast-math helpers ----------------
__device__ __forceinline__ ull pk2(float lo, float hi) {
    ull r; asm("mov.b64 %0,{%1,%2};" : "=l"(r) : "f"(lo), "f"(hi)); return r;
}
__device__ __forceinline__ void ffma2(ull& acc, ull a, ull b) {
    asm("fma.rn.f32x2 %0,%1,%2,%0;" : "+l"(acc) : "l"(a), "l"(b));
}
__device__ __forceinline__ void upk2(ull v, float& lo, float& hi) {
    asm("mov.b64 {%0,%1},%2;" : "=f"(lo), "=f"(hi) : "l"(v));
}
__device__ __forceinline__ float tanh_fast(float v) {
    float r; asm("tanh.approx.f32 %0,%1;" : "=f"(r) : "f"(v)); return r;
}
__device__ __forceinline__ float sigmoid_fast(float v) {
    return fmaf(tanh_fast(0.5f * v), 0.5f, 0.5f);
}
__device__ __forceinline__ unsigned f2tf32(float f) {
    unsigned u; asm("cvt.rna.tf32.f32 %0,%1;" : "=r"(u) : "f"(f)); return u;
}

// ---------------- device scratch (static, no allocation) ----------------
__device__ float g_tokenc[(NWn + 1) * CHn];
__device__ float g_texts[(size_t)Bn * Sn * INW0];
__device__ float g_xg[(size_t)Bn * Sn * G6];
__device__ float g_h0[(size_t)Bn * Sn * 256];
__device__ float g_h1[(size_t)Bn * Sn * 256];
__device__ float g_mlp[(size_t)Bn * Sn * Hn];
__device__ float g_emis[(size_t)Bn * Sn * Tn + 64];
__device__ float g_llh[Bn];
__device__ float g_w1t[Hn * 256];   // transposed mlp_w1: [128][256]

// ---------------- char CNN (480 threads; R13 proven) ----------------
__global__ void char_cnn_kernel(const float* __restrict__ char_emb,
                                const float* __restrict__ conv_w,
                                const float* __restrict__ conv_b,
                                const int* __restrict__ words) {
    __shared__ float s_emb[CLn + 2][CDn];
    __shared__ float s_w[CHn * CDn * 3];
    __shared__ float s_out[CHn * CLn];
    __shared__ int   s_idx[CLn];
    int tid = threadIdx.x;
    int blk = blockIdx.x;
    if (blk == 0) {
        if (tid < CHn) g_tokenc[tid] = 0.f;
        return;
    }
    int w = blk - 1;
    if (tid < CLn) s_idx[tid] = words[w * CLn + tid];
    for (int i = tid; i < CHn * CDn * 3; i += blockDim.x) s_w[i] = conv_w[i];
    if (tid < CDn) { s_emb[0][tid] = 0.f; s_emb[CLn + 1][tid] = 0.f; }
    __syncthreads();
    if (tid < CLn * CDn) {
        int t = tid / CDn, d = tid % CDn;
        s_emb[t + 1][d] = char_emb[s_idx[t] * CDn + d];
    }
    __syncthreads();
    {
        int ch = tid / CLn, t = tid % CLn;
        float acc = conv_b[ch];
        const float* wr = &s_w[ch * CDn * 3];
#pragma unroll
        for (int d = 0; d < CDn; ++d) {
            acc += s_emb[t][d]     * wr[d * 3 + 0];
            acc += s_emb[t + 1][d] * wr[d * 3 + 1];
            acc += s_emb[t + 2][d] * wr[d * 3 + 2];
        }
        s_out[ch * CLn + t] = fmaxf(acc, 0.f);
    }
    __syncthreads();
    if (tid < CHn) {
        float m = s_out[tid * CLn];
#pragma unroll
        for (int t = 1; t < CLn; ++t) m = fmaxf(m, s_out[tid * CLn + t]);
        g_tokenc[(w + 1) * CHn + tid] = m;
    }
}

// ---------------- build texts ----------------
__global__ void build_texts_kernel(const float* __restrict__ word_emb,
                                   const int* __restrict__ tokens,
                                   const int* __restrict__ cwi) {
    int m = blockIdx.x;
    int tid = threadIdx.x;
    int tok = tokens[m];
    int ci = cwi[m];
    if (tid < Dn)
        g_texts[(size_t)m * INW0 + tid] = word_emb[(size_t)tok * Dn + tid];
    else if (tid < INW0)
        g_texts[(size_t)m * INW0 + tid] = g_tokenc[ci * CHn + (tid - Dn)];
}

// ---------------- transpose mlp_w1 [256][128] -> [128][256] ----------------
__global__ void transpose_w1_kernel(const float* __restrict__ w1) {
    __shared__ float tile[32][33];
    int bx = blockIdx.x % 4, by = blockIdx.x / 4;
    int tx = threadIdx.x % 32, ty = threadIdx.x / 32;
#pragma unroll
    for (int r = 0; r < 4; ++r) {
        int row = ty + r * 8;
        tile[row][tx] = w1[(size_t)(by * 32 + row) * Hn + bx * 32 + tx];
    }
    __syncthreads();
#pragma unroll
    for (int r = 0; r < 4; ++r) {
        int row = ty + r * 8;
        g_w1t[(size_t)(bx * 32 + row) * 256 + by * 32 + tx] = tile[tx][row];
    }
}

#define PA 133
#define PW 69

// ---------------- tf32 GEMM 128x128 tile, 8 warps (2m x 4n), reg-prefetch ----------------
// C[M][N] = A[M][K] * W^T + bias; W is [N][K]. M%128==0, N%128==0.
__global__ void __launch_bounds__(256)
gemm_tf32_128_kernel(const float* __restrict__ A,
                     const float* __restrict__ W,
                     const float* __restrict__ bias,
                     float* __restrict__ C,
                     int M, int N, int K) {
    __shared__ float As[16][PA];
    __shared__ float Ws[16][PA];
    int tid = threadIdx.x;
    int warp = tid >> 5, lane = tid & 31;
    int wm = warp & 1, wn = warp >> 1;       // 2 m-groups of 64, 4 n-groups of 32
    int group = lane >> 2, tig = lane & 3;
    int m0 = blockIdx.y * 128, n0 = blockIdx.x * 128;
    float acc[4][4][4];
#pragma unroll
    for (int i = 0; i < 4; ++i)
#pragma unroll
        for (int j = 0; j < 4; ++j)
#pragma unroll
            for (int c = 0; c < 4; ++c) acc[i][j][c] = 0.f;

    int lkk = tid % 16;
    int li = tid / 16;
    int ktiles = (K + 15) / 16;
    float rA[8], rW[8];
#pragma unroll
    for (int l = 0; l < 8; ++l) {
        rA[l] = (lkk < K) ? A[(size_t)(m0 + li + l * 16) * K + lkk] : 0.f;
        rW[l] = (lkk < K) ? W[(size_t)(n0 + li + l * 16) * K + lkk] : 0.f;
    }

    for (int kt = 0; kt < ktiles; ++kt) {
#pragma unroll
        for (int l = 0; l < 8; ++l) {
            As[lkk][li + l * 16] = __uint_as_float(f2tf32(rA[l]));
            Ws[lkk][li + l * 16] = __uint_as_float(f2tf32(rW[l]));
        }
        __syncthreads();
        if (kt + 1 < ktiles) {
            int k = (kt + 1) * 16 + lkk;
#pragma unroll
            for (int l = 0; l < 8; ++l) {
                rA[l] = (k < K) ? A[(size_t)(m0 + li + l * 16) * K + k] : 0.f;
                rW[l] = (k < K) ? W[(size_t)(n0 + li + l * 16) * K + k] : 0.f;
            }
        }
#pragma unroll
        for (int k8 = 0; k8 < 2; ++k8) {
            int kb = k8 * 8;
            unsigned a[4][4], b[4][2];
#pragma unroll
            for (int mt = 0; mt < 4; ++mt) {
                int mb = wm * 64 + mt * 16;
                a[mt][0] = __float_as_uint(As[kb + tig][mb + group]);
                a[mt][1] = __float_as_uint(As[kb + tig][mb + group + 8]);
                a[mt][2] = __float_as_uint(As[kb + tig + 4][mb + group]);
                a[mt][3] = __float_as_uint(As[kb + tig + 4][mb + group + 8]);
            }
#pragma unroll
            for (int nt = 0; nt < 4; ++nt) {
                int nb = wn * 32 + nt * 8;
                b[nt][0] = __float_as_uint(Ws[kb + tig][nb + group]);
                b[nt][1] = __float_as_uint(Ws[kb + tig + 4][nb + group]);
            }
#pragma unroll
            for (int mt = 0; mt < 4; ++mt)
#pragma unroll
                for (int nt = 0; nt < 4; ++nt) {
                    asm volatile(
                        "mma.sync.aligned.m16n8k8.row.col.f32.tf32.tf32.f32 "
                        "{%0,%1,%2,%3},{%4,%5,%6,%7},{%8,%9},{%0,%1,%2,%3};"
                        : "+f"(acc[mt][nt][0]), "+f"(acc[mt][nt][1]),
                          "+f"(acc[mt][nt][2]), "+f"(acc[mt][nt][3])
                        : "r"(a[mt][0]), "r"(a[mt][1]), "r"(a[mt][2]), "r"(a[mt][3]),
                          "r"(b[nt][0]), "r"(b[nt][1]));
                }
        }
        __syncthreads();
    }
#pragma unroll
    for (int mt = 0; mt < 4; ++mt) {
        int row = m0 + wm * 64 + mt * 16 + group;
#pragma unroll
        for (int nt = 0; nt < 4; ++nt) {
            int col = n0 + wn * 32 + nt * 8 + 2 * tig;
            float b0 = bias[col], b1 = bias[col + 1];
            C[(size_t)row * N + col]           = acc[mt][nt][0] + b0;
            C[(size_t)row * N + col + 1]       = acc[mt][nt][1] + b1;
            C[(size_t)(row + 8) * N + col]     = acc[mt][nt][2] + b0;
            C[(size_t)(row + 8) * N + col + 1] = acc[mt][nt][3] + b1;
        }
    }
}

// ---------------- tf32 GEMM 128x64 (R13 proven; mlp) ----------------
__global__ void __launch_bounds__(256)
gemm_tf32_kernel(const float* __restrict__ A,
                 const float* __restrict__ W,
                 const float* __restrict__ bias,
                 float* __restrict__ C,
                 int M, int N, int K, int relu) {
    __shared__ float As[16][PA];
    __shared__ float Ws[16][PW];
    int tid = threadIdx.x;
    int warp = tid >> 5, lane = tid & 31;
    int wm = warp & 3, wn = warp >> 2;
    int group = lane >> 2, tig = lane & 3;
    int m0 = blockIdx.y * 128, n0 = blockIdx.x * 64;
    float acc[2][4][4];
#pragma unroll
    for (int i = 0; i < 2; ++i)
#pragma unroll
        for (int j = 0; j < 4; ++j)
#pragma unroll
            for (int c = 0; c < 4; ++c) acc[i][j][c] = 0.f;

    int lkk = tid % 16;
    int li = tid / 16;
    int ktiles = (K + 15) / 16;
    float rA[8], rW[4];
#pragma unroll
    for (int l = 0; l < 8; ++l)
        rA[l] = (lkk < K) ? A[(size_t)(m0 + li + l * 16) * K + lkk] : 0.f;
#pragma unroll
    for (int l = 0; l < 4; ++l)
        rW[l] = (lkk < K) ? W[(size_t)(n0 + li + l * 16) * K + lkk] : 0.f;

    for (int kt = 0; kt < ktiles; ++kt) {
#pragma unroll
        for (int l = 0; l < 8; ++l)
            As[lkk][li + l * 16] = __uint_as_float(f2tf32(rA[l]));
#pragma unroll
        for (int l = 0; l < 4; ++l)
            Ws[lkk][li + l * 16] = __uint_as_float(f2tf32(rW[l]));
        __syncthreads();
        if (kt + 1 < ktiles) {
            int k = (kt + 1) * 16 + lkk;
#pragma unroll
            for (int l = 0; l < 8; ++l)
                rA[l] = (k < K) ? A[(size_t)(m0 + li + l * 16) * K + k] : 0.f;
#pragma unroll
            for (int l = 0; l < 4; ++l)
                rW[l] = (k < K) ? W[(size_t)(n0 + li + l * 16) * K + k] : 0.f;
        }
#pragma unroll
        for (int k8 = 0; k8 < 2; ++k8) {
            int kb = k8 * 8;
            unsigned a[2][4], b[4][2];
#pragma unroll
            for (int mt = 0; mt < 2; ++mt) {
                int mb = wm * 32 + mt * 16;
                a[mt][0] = __float_as_uint(As[kb + tig][mb + group]);
                a[mt][1] = __float_as_uint(As[kb + tig][mb + group + 8]);
                a[mt][2] = __float_as_uint(As[kb + tig + 4][mb + group]);
                a[mt][3] = __float_as_uint(As[kb + tig + 4][mb + group + 8]);
            }
#pragma unroll
            for (int nt = 0; nt < 4; ++nt) {
                int nb = wn * 32 + nt * 8;
                b[nt][0] = __float_as_uint(Ws[kb + tig][nb + group]);
                b[nt][1] = __float_as_uint(Ws[kb + tig + 4][nb + group]);
            }
#pragma unroll
            for (int mt = 0; mt < 2; ++mt)
#pragma unroll
                for (int nt = 0; nt < 4; ++nt) {
                    asm volatile(
                        "mma.sync.aligned.m16n8k8.row.col.f32.tf32.tf32.f32 "
                        "{%0,%1,%2,%3},{%4,%5,%6,%7},{%8,%9},{%0,%1,%2,%3};"
                        : "+f"(acc[mt][nt][0]), "+f"(acc[mt][nt][1]),
                          "+f"(acc[mt][nt][2]), "+f"(acc[mt][nt][3])
                        : "r"(a[mt][0]), "r"(a[mt][1]), "r"(a[mt][2]), "r"(a[mt][3]),
                          "r"(b[nt][0]), "r"(b[nt][1]));
                }
        }
        __syncthreads();
    }
#pragma unroll
    for (int mt = 0; mt < 2; ++mt) {
        int row = m0 + wm * 32 + mt * 16 + group;
#pragma unroll
        for (int nt = 0; nt < 4; ++nt) {
            int col = n0 + wn * 32 + nt * 8 + 2 * tig;
            float b0 = bias[col], b1 = bias[col + 1];
            float v0 = acc[mt][nt][0] + b0;
            float v1 = acc[mt][nt][1] + b1;
            float v2 = acc[mt][nt][2] + b0;
            float v3 = acc[mt][nt][3] + b1;
            if (relu) {
                v0 = fmaxf(v0, 0.f); v1 = fmaxf(v1, 0.f);
                v2 = fmaxf(v2, 0.f); v3 = fmaxf(v3, 0.f);
            }
            C[(size_t)row * N + col]           = v0;
            C[(size_t)row * N + col + 1]       = v1;
            C[(size_t)(row + 8) * N + col]     = v2;
            C[(size_t)(row + 8) * N + col + 1] = v3;
        }
    }
}

// ---------------- scalar SGEMM 128x64 (emissions; R8 proven) ----------------
__global__ void gemm_kernel(const float* __restrict__ A,
                            const float* __restrict__ W,
                            const float* __restrict__ bias,
                            float* __restrict__ C,
                            int M, int N, int K, int relu, int wNK) {
    __shared__ float As[16][129];
    __shared__ float Ws[16][65];
    int tid = threadIdx.x;
    int tx = tid % 16, ty = tid / 16;
    int m0 = blockIdx.y * 128, n0 = blockIdx.x * 64;
    float acc[8][4] = {};
    int ktiles = (K + 15) / 16;
    for (int kt = 0; kt < ktiles; ++kt) {
        int k0 = kt * 16;
#pragma unroll
        for (int l = 0; l < 8; ++l) {
            int e = tid + l * 256;
            int kk = e % 16, i = e / 16;
            int m = m0 + i, k = k0 + kk;
            As[kk][i] = (k < K && m < M) ? A[(size_t)m * K + k] : 0.f;
        }
#pragma unroll
        for (int l = 0; l < 4; ++l) {
            int e = tid + l * 256;
            int kk = e % 16, i = e / 16;
            int n = n0 + i, k = k0 + kk;
            float wv = 0.f;
            if (k < K && n < N)
                wv = wNK ? W[(size_t)n * K + k] : W[(size_t)k * N + n];
            Ws[kk][i] = wv;
        }
        __syncthreads();
#pragma unroll
        for (int kk = 0; kk < 16; ++kk) {
            float a[8], b[4];
#pragma unroll
            for (int i = 0; i < 8; ++i) a[i] = As[kk][ty * 8 + i];
#pragma unroll
            for (int j = 0; j < 4; ++j) b[j] = Ws[kk][tx * 4 + j];
#pragma unroll
            for (int i = 0; i < 8; ++i)
#pragma unroll
                for (int j = 0; j < 4; ++j)
                    acc[i][j] += a[i] * b[j];
        }
        __syncthreads();
    }
#pragma unroll
    for (int i = 0; i < 8; ++i) {
        int m = m0 + ty * 8 + i;
        if (m >= M) continue;
#pragma unroll
        for (int j = 0; j < 4; ++j) {
            int n = n0 + tx * 4 + j;
            if (n >= N) continue;
            float v = acc[i][j] + bias[n];
            if (relu) v = fmaxf(v, 0.f);
            C[(size_t)m * N + n] = v;
        }
    }
}

// ---------------- GRU scan (R13-exact): quad K-split, 1 barrier/step ----------------
#define GT2 512
__global__ void __launch_bounds__(GT2, 1)
gru_kernel(const float* __restrict__ xg,    // [B*S][768]
           const float* __restrict__ w_hh,  // [2][384][128]
           const float* __restrict__ b_hh,  // [2][384]
           const int* __restrict__ lens,
           float* __restrict__ out) {       // [B*S][256]
    __shared__ __align__(16) float sh_h[2][Hn];
    int tid = threadIdx.x;
    int u = tid >> 2;
    int q = tid & 3;
    int dir = blockIdx.x / Bn;
    int b = blockIdx.x % Bn;

    ull wr2[48];
    {
        const float* Wd = w_hh + (size_t)dir * G3 * Hn;
#pragma unroll
        for (int gg = 0; gg < 3; ++gg) {
            const float* row = Wd + (size_t)(gg * Hn + u) * Hn + 4 * q;
#pragma unroll
            for (int i = 0; i < 8; ++i) {
                ulonglong2 v = *(const ulonglong2*)(row + 16 * i);
                wr2[gg * 16 + 2 * i]     = v.x;
                wr2[gg * 16 + 2 * i + 1] = v.y;
            }
        }
    }
    float br = b_hh[dir * G3 + u];
    float bz = b_hh[dir * G3 + Hn + u];
    float bnn = b_hh[dir * G3 + 2 * Hn + u];
    int len = lens[b];
    const float* xgb = xg + (size_t)b * Sn * G6 + dir * G3;
    float* outb = out + (size_t)b * Sn * 256 + dir * Hn;

    if (tid < Hn) { sh_h[0][tid] = 0.f; sh_h[1][tid] = 0.f; }

    int s0 = dir ? (Sn - 1) : 0;
    float xr_n = xgb[(size_t)s0 * G6 + u];
    float xz_n = xgb[(size_t)s0 * G6 + Hn + u];
    float xn_n = xgb[(size_t)s0 * G6 + 2 * Hn + u];
    __syncthreads();

    int p = 0;
    for (int t = 0; t < Sn; ++t) {
        int s = dir ? (Sn - 1 - t) : t;
        float xr = xr_n, xz = xz_n, xn = xn_n;
        if (t + 1 < Sn) {
            int sn = dir ? (s - 1) : (s + 1);
            xr_n = xgb[(size_t)sn * G6 + u];
            xz_n = xgb[(size_t)sn * G6 + Hn + u];
            xn_n = xgb[(size_t)sn * G6 + 2 * Hn + u];
        }
        const ulonglong2* hbp = (const ulonglong2*)(&sh_h[p][0] + 4 * q);
        ull ar = pk2(0.f, 0.f), az = ar, an = ar;
#pragma unroll
        for (int i = 0; i < 8; ++i) {
            ulonglong2 hv2 = hbp[i * 4];
            ffma2(ar, wr2[2 * i],          hv2.x);
            ffma2(az, wr2[16 + 2 * i],     hv2.x);
            ffma2(an, wr2[32 + 2 * i],     hv2.x);
            ffma2(ar, wr2[2 * i + 1],      hv2.y);
            ffma2(az, wr2[16 + 2 * i + 1], hv2.y);
            ffma2(an, wr2[32 + 2 * i + 1], hv2.y);
        }
        float lo, hi;
        upk2(ar, lo, hi); float hr = lo + hi;
        upk2(az, lo, hi); float hz = lo + hi;
        upk2(an, lo, hi); float hn = lo + hi;
        hr += __shfl_xor_sync(0xffffffffu, hr, 1);
        hz += __shfl_xor_sync(0xffffffffu, hz, 1);
        hn += __shfl_xor_sync(0xffffffffu, hn, 1);
        hr += __shfl_xor_sync(0xffffffffu, hr, 2);
        hz += __shfl_xor_sync(0xffffffffu, hz, 2);
        hn += __shfl_xor_sync(0xffffffffu, hn, 2);
        float hp = sh_h[p][u];
        float r = sigmoid_fast(xr + hr + br);
        float z = sigmoid_fast(xz + hz + bz);
        float n = tanh_fast(fmaf(r, hn + bnn, xn));
        float hv = (s < len) ? ((1.f - z) * n + z * hp) : hp;
        if (q == 0) sh_h[p ^ 1][u] = hv;
        if (q == 1) outb[(size_t)s * 256 + u] = hv;
        p ^= 1;
        __syncthreads();
    }
}

// ---------------- CRF (fast exp/log) ----------------
__global__ void crf_kernel(const float* __restrict__ start,
                           const float* __restrict__ end_,
                           const float* __restrict__ trans,
                           const int* __restrict__ target,
                           const int* __restrict__ lens) {
    int b = blockIdx.x, lane = threadIdx.x;
    const float* E = g_emis + (size_t)b * Sn * Tn;
    const int* tgt = target + b * Sn;
    int len = lens[b];

    float partial = 0.f;
    for (int s = 1 + lane; s < Sn; s += 32) {
        if (s < len)
            partial += trans[tgt[s - 1] * Tn + tgt[s]] + E[s * Tn + tgt[s]];
    }
#pragma unroll
    for (int o = 16; o; o >>= 1) partial += __shfl_down_sync(0xffffffffu, partial, o);

    float tc[Tn];
    float alpha = -1e30f;
    if (lane < Tn) {
        alpha = start[lane] + E[lane];
#pragma unroll
        for (int i = 0; i < Tn; ++i) tc[i] = trans[i * Tn + lane];
    } else {
#pragma unroll
        for (int i = 0; i < Tn; ++i) tc[i] = 0.f;
    }
    for (int s = 1; s < Sn; ++s) {
        float av[Tn];
        float mx = -1e30f;
#pragma unroll
        for (int i = 0; i < Tn; ++i) {
            av[i] = __shfl_sync(0xffffffffu, alpha, i) + tc[i];
            mx = fmaxf(mx, av[i]);
        }
        float sum = 0.f;
#pragma unroll
        for (int i = 0; i < Tn; ++i) sum += __expf(av[i] - mx);
        float e = (lane < Tn) ? E[s * Tn + lane] : 0.f;
        float nw = mx + __logf(sum) + e;
        if (lane < Tn && s < len) alpha = nw;
    }
    float v = (lane < Tn) ? alpha + end_[lane] : -1e30f;
    float mx = v;
#pragma unroll
    for (int o = 16; o; o >>= 1) mx = fmaxf(mx, __shfl_xor_sync(0xffffffffu, mx, o));
    float se = __expf(v - mx);
#pragma unroll
    for (int o = 16; o; o >>= 1) se += __shfl_xor_sync(0xffffffffu, se, o);
    float logz = mx + __logf(se);
    if (lane == 0) {
        float score = partial + start[tgt[0]] + E[tgt[0]] + end_[tgt[len - 1]];
        g_llh[b] = score - logz;
    }
}

__global__ void finalize_kernel(const int* __restrict__ lens, float* __restrict__ out) {
    float sl = 0.f;
    float smk = 0.f;
    for (int b = 0; b < Bn; ++b) { sl += g_llh[b]; smk += (float)lens[b]; }
    out[0] = -sl / smk;
}

// ---------------- launch ----------------
extern "C" void kernel_launch(void* const* d_in, const int* in_sizes, int n_in,
                              void* d_out, int out_size) {
    const float* char_emb  = (const float*)d_in[0];
    const float* conv_w    = (const float*)d_in[1];
    const float* conv_b    = (const float*)d_in[2];
    const float* word_emb  = (const float*)d_in[3];
    const float* w_ih_l0   = (const float*)d_in[4];
    const float* w_hh_l0   = (const float*)d_in[5];
    const float* b_ih_l0   = (const float*)d_in[6];
    const float* b_hh_l0   = (const float*)d_in[7];
    const float* w_ih_l1   = (const float*)d_in[8];
    const float* w_hh_l1   = (const float*)d_in[9];
    const float* b_ih_l1   = (const float*)d_in[10];
    const float* b_hh_l1   = (const float*)d_in[11];
    const float* mlp_w1    = (const float*)d_in[12];
    const float* mlp_b1    = (const float*)d_in[13];
    const float* mlp_w2    = (const float*)d_in[14];
    const float* mlp_b2    = (const float*)d_in[15];
    const float* crf_start = (const float*)d_in[16];
    const float* crf_end   = (const float*)d_in[17];
    const float* crf_trans = (const float*)d_in[18];
    const int* char_words  = (const int*)d_in[19];
    const int* cwi         = (const int*)d_in[21];
    const int* tokens      = (const int*)d_in[22];
    const int* tokens_len  = (const int*)d_in[23];
    const int* target      = (const int*)d_in[24];
    float* out = (float*)d_out;

    void* pv;
    cudaGetSymbolAddress(&pv, g_texts); float* p_texts = (float*)pv;
    cudaGetSymbolAddress(&pv, g_xg);    float* p_xg    = (float*)pv;
    cudaGetSymbolAddress(&pv, g_h0);    float* p_h0    = (float*)pv;
    cudaGetSymbolAddress(&pv, g_h1);    float* p_h1    = (float*)pv;
    cudaGetSymbolAddress(&pv, g_mlp);   float* p_mlp   = (float*)pv;
    cudaGetSymbolAddress(&pv, g_emis);  float* p_emis  = (float*)pv;
    cudaGetSymbolAddress(&pv, g_w1t);   float* p_w1t   = (float*)pv;

    const int M = Bn * Sn;  // 16384

    char_cnn_kernel<<<NWn + 1, 480>>>(char_emb, conv_w, conv_b, char_words);
    transpose_w1_kernel<<<32, 256>>>(mlp_w1);
    build_texts_kernel<<<M, 352>>>(word_emb, tokens, cwi);
    gemm_tf32_128_kernel<<<dim3(G6 / 128, M / 128), 256>>>(p_texts, w_ih_l0, b_ih_l0,
                                                           p_xg, M, G6, INW0);
    gru_kernel<<<2 * Bn, GT2>>>(p_xg, w_hh_l0, b_hh_l0, tokens_len, p_h0);
    gemm_tf32_128_kernel<<<dim3(G6 / 128, M / 128), 256>>>(p_h0, w_ih_l1, b_ih_l1,
                                                           p_xg, M, G6, 256);
    gru_kernel<<<2 * Bn, GT2>>>(p_xg, w_hh_l1, b_hh_l1, tokens_len, p_h1);
    gemm_tf32_kernel<<<dim3(Hn / 64, M / 128), 256>>>(p_h1, p_w1t, mlp_b1, p_mlp,
                                                      M, Hn, 256, 1);
    gemm_kernel<<<dim3(1, M / 128), 256>>>(p_mlp, mlp_w2, mlp_b2, p_emis,
                                           M, Tn, Hn, 0, 0);
    crf_kernel<<<Bn, 32>>>(crf_start, crf_end, crf_trans, target, tokens_len);
    finalize_kernel<<<1, 1>>>(tokens_len, out);
}